// round 1
// baseline (speedup 1.0000x reference)
#include <cuda_runtime.h>
#include <cuda_fp16.h>
#include <math.h>

#define BB     64
#define ICAPS  2048
#define KDIM   8
#define NCAPS  32
#define DDIM   16
#define JD     512   // NCAPS*DDIM
#define SP_C   0.5413248546129181f

// scratch (device globals — no allocations allowed)
__device__ __half g_uhat[(size_t)BB * ICAPS * JD];   // 134 MB fp16 predictions
__device__ float  g_s0[BB * JD];
__device__ float  g_s1[BB * JD];
__device__ float  g_s2[BB * JD];
__device__ float  g_v0[BB * JD];
__device__ float  g_v01[BB * JD];   // v0 + v1 (for b2 = dot(u, v0+v1))

__device__ __forceinline__ float softplusf(float z) {
    return z > 15.f ? z : log1pf(__expf(z));
}

// ---------------------------------------------------------------------------
// init: zero the three s accumulators (needed every replay; atomics add into them)
// ---------------------------------------------------------------------------
__global__ void init_kernel() {
    int idx = blockIdx.x * blockDim.x + threadIdx.x;
    if (idx < BB * JD) { g_s0[idx] = 0.f; g_s1[idx] = 0.f; g_s2[idx] = 0.f; }
}

// ---------------------------------------------------------------------------
// pass0: W = loc + (1e-5 + softplus(C + sraw))*eps  (computed on the fly),
//        u_hat[b,i,jd] = sum_k W[i,jd,k] * x[b,i,k]  -> fp16 store,
//        s0[b,jd] += u_hat (uniform-c iteration, scaled by 1/32 later).
// Block <-> i-chunk; thread t <-> jd; inner loop over all 64 b (W reused from regs).
// s0 partials live in smem (each thread owns slots b*512+t exclusively).
// ---------------------------------------------------------------------------
__global__ void __launch_bounds__(512) pass0_kernel(
    const float* __restrict__ x, const float* __restrict__ loc,
    const float* __restrict__ sraw, const float* __restrict__ eps, int t_i)
{
    extern __shared__ float smem[];
    float* s0_s = smem;              // BB*JD floats (128 KB)
    float* x_s  = smem + BB * JD;    // BB*KDIM floats (2 KB)
    const int t = threadIdx.x;

    #pragma unroll
    for (int idx = t; idx < BB * JD; idx += 512) s0_s[idx] = 0.f;

    const int i0 = blockIdx.x * t_i;
    for (int ii = 0; ii < t_i; ++ii) {
        const int i = i0 + ii;
        // --- build W row for this (i, jd): 8 coefficients in registers ---
        const size_t wb = ((size_t)i * JD + t) * KDIM;
        float4 l0 = *(const float4*)(loc  + wb), l1 = *(const float4*)(loc  + wb + 4);
        float4 r0 = *(const float4*)(sraw + wb), r1 = *(const float4*)(sraw + wb + 4);
        float4 e0 = *(const float4*)(eps  + wb), e1 = *(const float4*)(eps  + wb + 4);
        float w0 = l0.x + (1e-5f + softplusf(SP_C + r0.x)) * e0.x;
        float w1 = l0.y + (1e-5f + softplusf(SP_C + r0.y)) * e0.y;
        float w2 = l0.z + (1e-5f + softplusf(SP_C + r0.z)) * e0.z;
        float w3 = l0.w + (1e-5f + softplusf(SP_C + r0.w)) * e0.w;
        float w4 = l1.x + (1e-5f + softplusf(SP_C + r1.x)) * e1.x;
        float w5 = l1.y + (1e-5f + softplusf(SP_C + r1.y)) * e1.y;
        float w6 = l1.z + (1e-5f + softplusf(SP_C + r1.z)) * e1.z;
        float w7 = l1.w + (1e-5f + softplusf(SP_C + r1.w)) * e1.w;

        __syncthreads();   // protect x_s from overwrite while prior iter reads
        x_s[t] = x[((size_t)(t >> 3) * ICAPS + i) * KDIM + (t & 7)];
        __syncthreads();

        const float4* xs4 = (const float4*)x_s;
        #pragma unroll 4
        for (int b = 0; b < BB; ++b) {
            float4 xa = xs4[2 * b], xb = xs4[2 * b + 1];
            float u = w0 * xa.x + w1 * xa.y + w2 * xa.z + w3 * xa.w
                    + w4 * xb.x + w5 * xb.y + w6 * xb.z + w7 * xb.w;
            s0_s[b * JD + t] += u;
            g_uhat[((size_t)b * ICAPS + i) * JD + t] = __float2half(u);
        }
    }
    __syncthreads();
    #pragma unroll
    for (int idx = t; idx < BB * JD; idx += 512)
        atomicAdd(&g_s0[idx], s0_s[idx]);
}

// ---------------------------------------------------------------------------
// squash: mode 0: v0 = squash(s0/32)          -> g_v0
//         mode 1: g_v01 = g_v0 + squash(s1)
//         mode 2: out_v = squash(s2)
// One thread per (b,j) vector of 16.
// ---------------------------------------------------------------------------
__global__ void squash_kernel(int mode, float* __restrict__ out_v)
{
    int idx = blockIdx.x * blockDim.x + threadIdx.x;
    if (idx >= BB * NCAPS) return;
    const float* s_in = (mode == 0) ? g_s0 : (mode == 1) ? g_s1 : g_s2;
    float pre = (mode == 0) ? (1.f / NCAPS) : 1.f;
    float s[DDIM];
    const float4* s4 = (const float4*)(s_in + (size_t)idx * DDIM);
    #pragma unroll
    for (int q = 0; q < 4; ++q) {
        float4 p = s4[q];
        s[4*q+0] = p.x * pre; s[4*q+1] = p.y * pre; s[4*q+2] = p.z * pre; s[4*q+3] = p.w * pre;
    }
    float s2 = 0.f;
    #pragma unroll
    for (int d = 0; d < DDIM; ++d) s2 = fmaf(s[d], s[d], s2);
    float sc = s2 / ((1.f + s2) * sqrtf(s2 + 1e-7f));

    float* dst = (mode == 0) ? g_v0 : (mode == 1) ? g_v01 : out_v;
    float4 o[4];
    #pragma unroll
    for (int q = 0; q < 4; ++q) {
        o[q].x = s[4*q+0] * sc; o[q].y = s[4*q+1] * sc;
        o[q].z = s[4*q+2] * sc; o[q].w = s[4*q+3] * sc;
    }
    if (mode == 1) {   // add v0
        const float4* b4 = (const float4*)(g_v0 + (size_t)idx * DDIM);
        #pragma unroll
        for (int q = 0; q < 4; ++q) {
            float4 p = b4[q];
            o[q].x += p.x; o[q].y += p.y; o[q].z += p.z; o[q].w += p.w;
        }
    }
    float4* d4 = (float4*)(dst + (size_t)idx * DDIM);
    #pragma unroll
    for (int q = 0; q < 4; ++q) d4[q] = o[q];
}

// ---------------------------------------------------------------------------
// routing pass: per (b,i): logits = dot(u_hat, v_eff) over d; c = softmax over j
// (warp lanes); s += c*u_hat (register accumulation over i, one REDG burst).
// LAST pass also writes c to the routing_weights output.
// ---------------------------------------------------------------------------
template<bool LAST>
__global__ void __launch_bounds__(256) route_kernel(float* __restrict__ c_out)
{
    const int b    = blockIdx.x;
    const int lane = threadIdx.x & 31;
    const int w    = threadIdx.x >> 5;            // 8 warps

    const float* vin = LAST ? g_v01 : g_v0;
    float v[DDIM];
    {
        const float4* v4 = (const float4*)(vin + ((size_t)b * NCAPS + lane) * DDIM);
        #pragma unroll
        for (int q = 0; q < 4; ++q) {
            float4 p = v4[q];
            v[4*q+0] = p.x; v[4*q+1] = p.y; v[4*q+2] = p.z; v[4*q+3] = p.w;
        }
    }
    float sp[DDIM];
    #pragma unroll
    for (int d = 0; d < DDIM; ++d) sp[d] = 0.f;

    const int per_chunk = ICAPS / 8;              // gridDim.y = 8 -> 256 i per block
    int i = blockIdx.y * per_chunk + w;
    for (int it = 0; it < per_chunk / 8; ++it, i += 8) {
        const uint4* uh4 = (const uint4*)(g_uhat + ((size_t)b * ICAPS + i) * JD
                                          + (size_t)lane * DDIM);
        uint4 p0 = uh4[0], p1 = uh4[1];
        float u[DDIM];
        const __half2* h0 = (const __half2*)&p0;
        const __half2* h1 = (const __half2*)&p1;
        #pragma unroll
        for (int q = 0; q < 4; ++q) {
            float2 f0 = __half22float2(h0[q]);
            u[2*q+0] = f0.x; u[2*q+1] = f0.y;
            float2 f1 = __half22float2(h1[q]);
            u[8+2*q+0] = f1.x; u[8+2*q+1] = f1.y;
        }
        float bl = 0.f;
        #pragma unroll
        for (int d = 0; d < DDIM; ++d) bl = fmaf(u[d], v[d], bl);
        // softmax over the 32 output caps (one per lane)
        float m = bl;
        #pragma unroll
        for (int off = 16; off; off >>= 1)
            m = fmaxf(m, __shfl_xor_sync(0xffffffffu, m, off));
        float e = __expf(bl - m);
        float ssum = e;
        #pragma unroll
        for (int off = 16; off; off >>= 1)
            ssum += __shfl_xor_sync(0xffffffffu, ssum, off);
        float c = e / ssum;
        #pragma unroll
        for (int d = 0; d < DDIM; ++d) sp[d] = fmaf(c, u[d], sp[d]);
        if (LAST)
            c_out[((size_t)b * ICAPS + i) * NCAPS + lane] = c;
    }
    float* s_out = LAST ? g_s2 : g_s1;
    float* dst = s_out + ((size_t)b * NCAPS + lane) * DDIM;
    #pragma unroll
    for (int d = 0; d < DDIM; ++d) atomicAdd(dst + d, sp[d]);
}

// ---------------------------------------------------------------------------
extern "C" void kernel_launch(void* const* d_in, const int* in_sizes, int n_in,
                              void* d_out, int out_size)
{
    const float* x    = (const float*)d_in[0];
    const float* loc  = (const float*)d_in[1];
    const float* sraw = (const float*)d_in[2];
    const float* eps  = (const float*)d_in[3];
    float* out_v = (float*)d_out;                 // [B, NCAPS, DDIM]
    float* out_c = out_v + BB * NCAPS * DDIM;     // [B, ICAPS, NCAPS]

    const int SMEM0 = (BB * JD + BB * KDIM) * (int)sizeof(float);  // 133120 B
    cudaFuncSetAttribute(pass0_kernel, cudaFuncAttributeMaxDynamicSharedMemorySize, SMEM0);

    init_kernel<<<(BB * JD + 255) / 256, 256>>>();
    pass0_kernel<<<256, 512, SMEM0>>>(x, loc, sraw, eps, ICAPS / 256);
    squash_kernel<<<(BB * NCAPS + 255) / 256, 256>>>(0, out_v);   // v0
    route_kernel<false><<<dim3(BB, 8), 256>>>(nullptr);           // iter 1 -> s1
    squash_kernel<<<(BB * NCAPS + 255) / 256, 256>>>(1, out_v);   // v01 = v0 + v1
    route_kernel<true><<<dim3(BB, 8), 256>>>(out_c);              // iter 2 -> s2, c
    squash_kernel<<<(BB * NCAPS + 255) / 256, 256>>>(2, out_v);   // v2 -> output
}

// round 2
// speedup vs baseline: 1.2359x; 1.2359x over previous
#include <cuda_runtime.h>
#include <cuda_fp16.h>
#include <math.h>

#define BB     64
#define ICAPS  2048
#define KDIM   8
#define NCAPS  32
#define DDIM   16
#define JD     512           // NCAPS*DDIM
#define SP_C   0.5413248546129181f
#define NBLK0  256           // pass0 blocks (8 i each)

// ---- device scratch (no allocations allowed) ----
__device__ __half g_uhat[(size_t)BB * ICAPS * JD];     // 134 MB fp16 predictions
__device__ float  g_s0_part[NBLK0][BB * JD];           // 32 MB per-block partials
__device__ float  g_s0[BB * JD];
__device__ float  g_s1[BB * JD];
__device__ float  g_s2[BB * JD];

__device__ __forceinline__ float softplusf(float z) {
    // fast softplus; for z>15 softplus(z)==z to fp32 precision
    return z > 15.f ? z : __logf(1.f + __expf(z));
}

// ---------------------------------------------------------------------------
// init: zero routing accumulators (atomically added into each replay)
// ---------------------------------------------------------------------------
__global__ void init_kernel() {
    int idx = blockIdx.x * blockDim.x + threadIdx.x;
    if (idx < BB * JD) { g_s1[idx] = 0.f; g_s2[idx] = 0.f; }
}

// ---------------------------------------------------------------------------
// pass0: W = loc + (1e-5 + softplus(C + sraw))*eps  on the fly,
//        u_hat[b,i,jd] = sum_k W[i,jd,k]*x[b,i,k]  -> half2 store,
//        per-block s0 partial in smem -> g_s0_part (no atomics).
// 256 threads; thread t owns jd = {2t, 2t+1}. Block handles 8 consecutive i.
// ---------------------------------------------------------------------------
__global__ void __launch_bounds__(256) pass0_kernel(
    const float* __restrict__ x, const float* __restrict__ loc,
    const float* __restrict__ sraw, const float* __restrict__ eps)
{
    extern __shared__ float smem[];
    float2* s0p = (float2*)smem;          // [b*256 + t] -> (jd=2t, jd=2t+1)
    float*  x_s = smem + BB * JD;         // 512 floats
    const int t = threadIdx.x;

    #pragma unroll
    for (int idx = t; idx < BB * JD / 2; idx += 256)
        s0p[idx] = make_float2(0.f, 0.f);

    const int i0 = blockIdx.x * 8;
    // prefetch first i's parameters (16 floats per array per thread)
    const float4* lp = (const float4*)(loc  + ((size_t)i0 * JD + 2 * t) * KDIM);
    const float4* rp = (const float4*)(sraw + ((size_t)i0 * JD + 2 * t) * KDIM);
    const float4* ep = (const float4*)(eps  + ((size_t)i0 * JD + 2 * t) * KDIM);
    float4 Pl[4], Pr[4], Pe[4];
    #pragma unroll
    for (int q = 0; q < 4; ++q) { Pl[q] = lp[q]; Pr[q] = rp[q]; Pe[q] = ep[q]; }

    for (int ii = 0; ii < 8; ++ii) {
        const int i = i0 + ii;
        // build 16 W coefficients from prefetched params
        float W[16];
        #pragma unroll
        for (int q = 0; q < 4; ++q) {
            const float* l = (const float*)&Pl[q];
            const float* r = (const float*)&Pr[q];
            const float* e = (const float*)&Pe[q];
            #pragma unroll
            for (int u = 0; u < 4; ++u)
                W[4 * q + u] = l[u] + (1e-5f + softplusf(SP_C + r[u])) * e[u];
        }
        // prefetch next i
        if (ii < 7) {
            lp += JD * KDIM / 4; rp += JD * KDIM / 4; ep += JD * KDIM / 4;
            #pragma unroll
            for (int q = 0; q < 4; ++q) { Pl[q] = lp[q]; Pr[q] = rp[q]; Pe[q] = ep[q]; }
        }
        __syncthreads();   // previous b-loop readers of x_s done
        {
            int m0 = t, m1 = t + 256;
            x_s[m0] = x[((size_t)(m0 >> 3) * ICAPS + i) * KDIM + (m0 & 7)];
            x_s[m1] = x[((size_t)(m1 >> 3) * ICAPS + i) * KDIM + (m1 & 7)];
        }
        __syncthreads();

        const float4* xs4 = (const float4*)x_s;
        __half2* up = (__half2*)(g_uhat + (size_t)i * JD + 2 * t);
        const size_t bstride = (size_t)ICAPS * JD / 2;   // in half2 units
        #pragma unroll 4
        for (int b = 0; b < BB; ++b) {
            float4 xa = xs4[2 * b], xb = xs4[2 * b + 1];
            float u0 = W[0]*xa.x + W[1]*xa.y + W[2]*xa.z + W[3]*xa.w
                     + W[4]*xb.x + W[5]*xb.y + W[6]*xb.z + W[7]*xb.w;
            float u1 = W[8]*xa.x + W[9]*xa.y + W[10]*xa.z + W[11]*xa.w
                     + W[12]*xb.x + W[13]*xb.y + W[14]*xb.z + W[15]*xb.w;
            float2 acc = s0p[b * 256 + t];
            acc.x += u0; acc.y += u1;
            s0p[b * 256 + t] = acc;
            up[(size_t)b * bstride] = __floats2half2_rn(u0, u1);
        }
    }
    __syncthreads();
    float* part = g_s0_part[blockIdx.x];
    const float* s0f = smem;
    #pragma unroll
    for (int idx = t; idx < BB * JD; idx += 256) part[idx] = s0f[idx];
}

// ---------------------------------------------------------------------------
// reduce0: sum the 256 per-block partials -> g_s0 (deterministic)
// ---------------------------------------------------------------------------
__global__ void reduce0_kernel() {
    int idx = blockIdx.x * blockDim.x + threadIdx.x;   // 32768 total
    float a = 0.f;
    #pragma unroll 8
    for (int blk = 0; blk < NBLK0; ++blk) a += g_s0_part[blk][idx];
    g_s0[idx] = a;
}

// ---------------------------------------------------------------------------
// route pass. Computes v in-kernel from g_s0 (and g_s1 for LAST):
//   !LAST: v = v0 = squash(s0/32)            -> accumulates s1
//    LAST: v = v0 + squash(s1)               -> accumulates s2, writes c
// Mapping: block (b, chunk); 4 warps; lane <-> output cap j; 4 i per iter.
// Softmax without max-subtraction (logits bounded), interleaved butterflies.
// ---------------------------------------------------------------------------
template<bool LAST>
__global__ void __launch_bounds__(128) route_kernel(float* __restrict__ c_out)
{
    __shared__ float v_s[JD];
    __shared__ float sp_s[4][NCAPS * 17 + 1];
    const int b = blockIdx.x;
    const int tid = threadIdx.x, lane = tid & 31, w = tid >> 5;

    if (tid < NCAPS) {   // per-j squash (redundant per block; tiny)
        float tv[DDIM]; float n = 0.f;
        const float4* s4 = (const float4*)(g_s0 + ((size_t)b * NCAPS + tid) * DDIM);
        #pragma unroll
        for (int q = 0; q < 4; ++q) {
            float4 p = s4[q];
            tv[4*q+0] = p.x * (1.f/NCAPS); tv[4*q+1] = p.y * (1.f/NCAPS);
            tv[4*q+2] = p.z * (1.f/NCAPS); tv[4*q+3] = p.w * (1.f/NCAPS);
        }
        #pragma unroll
        for (int d = 0; d < DDIM; ++d) n = fmaf(tv[d], tv[d], n);
        float sc = n / ((1.f + n) * sqrtf(n + 1e-7f));
        float vout[DDIM];
        #pragma unroll
        for (int d = 0; d < DDIM; ++d) vout[d] = tv[d] * sc;
        if (LAST) {
            float t1[DDIM]; float n1 = 0.f;
            const float4* s14 = (const float4*)(g_s1 + ((size_t)b * NCAPS + tid) * DDIM);
            #pragma unroll
            for (int q = 0; q < 4; ++q) {
                float4 p = s14[q];
                t1[4*q+0] = p.x; t1[4*q+1] = p.y; t1[4*q+2] = p.z; t1[4*q+3] = p.w;
            }
            #pragma unroll
            for (int d = 0; d < DDIM; ++d) n1 = fmaf(t1[d], t1[d], n1);
            float sc1 = n1 / ((1.f + n1) * sqrtf(n1 + 1e-7f));
            #pragma unroll
            for (int d = 0; d < DDIM; ++d) vout[d] += t1[d] * sc1;
        }
        #pragma unroll
        for (int d = 0; d < DDIM; ++d) v_s[tid * DDIM + d] = vout[d];
    }
    __syncthreads();

    float v[DDIM];
    {
        const float4* v4 = (const float4*)(v_s + lane * DDIM);
        #pragma unroll
        for (int q = 0; q < 4; ++q) {
            float4 p = v4[q];
            v[4*q+0] = p.x; v[4*q+1] = p.y; v[4*q+2] = p.z; v[4*q+3] = p.w;
        }
    }
    float sp[DDIM];
    #pragma unroll
    for (int d = 0; d < DDIM; ++d) sp[d] = 0.f;

    const int per_block = ICAPS / 16;          // gridDim.y = 16 -> 128 i
    const int per_warp  = per_block / 4;       // 32 i per warp
    const int ibase = blockIdx.y * per_block + w * per_warp;
    const __half2* ubase = (const __half2*)g_uhat
                         + (size_t)b * ICAPS * (JD/2) + lane * (DDIM/2);

    for (int it = 0; it < per_warp / 4; ++it) {
        const int i = ibase + it * 4;
        uint4 ua[4], ub[4];
        #pragma unroll
        for (int r = 0; r < 4; ++r) {
            const uint4* p = (const uint4*)(ubase + (size_t)(i + r) * (JD/2));
            ua[r] = p[0]; ub[r] = p[1];
        }
        float ev[4];
        #pragma unroll
        for (int r = 0; r < 4; ++r) {
            float bl = 0.f;
            const __half2* ha = (const __half2*)&ua[r];
            const __half2* hb = (const __half2*)&ub[r];
            #pragma unroll
            for (int q = 0; q < 4; ++q) {
                float2 f = __half22float2(ha[q]);
                bl = fmaf(f.x, v[2*q],   fmaf(f.y, v[2*q+1],   bl));
            }
            #pragma unroll
            for (int q = 0; q < 4; ++q) {
                float2 f = __half22float2(hb[q]);
                bl = fmaf(f.x, v[8+2*q], fmaf(f.y, v[8+2*q+1], bl));
            }
            ev[r] = __expf(bl);   // logits bounded: no max-subtraction needed
        }
        float t0 = ev[0], t1 = ev[1], t2 = ev[2], t3 = ev[3];
        #pragma unroll
        for (int off = 16; off; off >>= 1) {   // 4 interleaved butterflies
            t0 += __shfl_xor_sync(0xffffffffu, t0, off);
            t1 += __shfl_xor_sync(0xffffffffu, t1, off);
            t2 += __shfl_xor_sync(0xffffffffu, t2, off);
            t3 += __shfl_xor_sync(0xffffffffu, t3, off);
        }
        float sums[4] = {t0, t1, t2, t3};
        #pragma unroll
        for (int r = 0; r < 4; ++r) {
            float c = __fdividef(ev[r], sums[r]);
            const __half2* ha = (const __half2*)&ua[r];
            const __half2* hb = (const __half2*)&ub[r];
            #pragma unroll
            for (int q = 0; q < 4; ++q) {
                float2 f = __half22float2(ha[q]);
                sp[2*q]     = fmaf(c, f.x, sp[2*q]);
                sp[2*q+1]   = fmaf(c, f.y, sp[2*q+1]);
            }
            #pragma unroll
            for (int q = 0; q < 4; ++q) {
                float2 f = __half22float2(hb[q]);
                sp[8+2*q]   = fmaf(c, f.x, sp[8+2*q]);
                sp[8+2*q+1] = fmaf(c, f.y, sp[8+2*q+1]);
            }
            if (LAST)
                c_out[((size_t)b * ICAPS + i + r) * NCAPS + lane] = c;
        }
    }
    // cross-warp reduce in smem, then one REDG burst (4x fewer atomics)
    #pragma unroll
    for (int d = 0; d < DDIM; ++d) sp_s[w][lane * 17 + d] = sp[d];
    __syncthreads();
    float* s_out = (LAST ? g_s2 : g_s1) + (size_t)b * JD;
    #pragma unroll
    for (int q = 0; q < 4; ++q) {
        int idx = tid * 4 + q;          // 0..511
        int j = idx >> 4, d = idx & 15;
        float a = sp_s[0][j*17+d] + sp_s[1][j*17+d]
                + sp_s[2][j*17+d] + sp_s[3][j*17+d];
        atomicAdd(s_out + idx, a);
    }
}

// ---------------------------------------------------------------------------
// final squash: out_v = squash(s2)
// ---------------------------------------------------------------------------
__global__ void squash_final_kernel(float* __restrict__ out_v)
{
    int idx = blockIdx.x * blockDim.x + threadIdx.x;
    if (idx >= BB * NCAPS) return;
    float s[DDIM]; float n = 0.f;
    const float4* s4 = (const float4*)(g_s2 + (size_t)idx * DDIM);
    #pragma unroll
    for (int q = 0; q < 4; ++q) {
        float4 p = s4[q];
        s[4*q+0] = p.x; s[4*q+1] = p.y; s[4*q+2] = p.z; s[4*q+3] = p.w;
    }
    #pragma unroll
    for (int d = 0; d < DDIM; ++d) n = fmaf(s[d], s[d], n);
    float sc = n / ((1.f + n) * sqrtf(n + 1e-7f));
    float4* d4 = (float4*)(out_v + (size_t)idx * DDIM);
    #pragma unroll
    for (int q = 0; q < 4; ++q) {
        float4 o;
        o.x = s[4*q+0] * sc; o.y = s[4*q+1] * sc;
        o.z = s[4*q+2] * sc; o.w = s[4*q+3] * sc;
        d4[q] = o;
    }
}

// ---------------------------------------------------------------------------
extern "C" void kernel_launch(void* const* d_in, const int* in_sizes, int n_in,
                              void* d_out, int out_size)
{
    const float* x    = (const float*)d_in[0];
    const float* loc  = (const float*)d_in[1];
    const float* sraw = (const float*)d_in[2];
    const float* eps  = (const float*)d_in[3];
    float* out_v = (float*)d_out;                 // [B, NCAPS, DDIM]
    float* out_c = out_v + BB * NCAPS * DDIM;     // [B, ICAPS, NCAPS]

    const int SMEM0 = (BB * JD + BB * KDIM) * (int)sizeof(float);  // 133120 B
    cudaFuncSetAttribute(pass0_kernel, cudaFuncAttributeMaxDynamicSharedMemorySize, SMEM0);

    init_kernel<<<(BB * JD + 255) / 256, 256>>>();
    pass0_kernel<<<NBLK0, 256, SMEM0>>>(x, loc, sraw, eps);
    reduce0_kernel<<<(BB * JD) / 256, 256>>>();
    route_kernel<false><<<dim3(BB, 16), 128>>>(nullptr);   // iter 1 -> s1
    route_kernel<true><<<dim3(BB, 16), 128>>>(out_c);      // iter 2 -> s2, c
    squash_final_kernel<<<(BB * NCAPS + 63) / 64, 64>>>(out_v);
}

// round 3
// speedup vs baseline: 1.6785x; 1.3581x over previous
#include <cuda_runtime.h>
#include <cuda_fp16.h>
#include <math.h>

#define BB     64
#define ICAPS  2048
#define KDIM   8
#define NCAPS  32
#define DDIM   16
#define JD     512           // NCAPS*DDIM
#define SP_C   0.5413248546129181f
#define IPB    4             // i per pass0 block

typedef unsigned long long ull;

// ---- device scratch (no allocations allowed) ----
__device__ __half g_uhat[(size_t)BB * ICAPS * JD];     // 134 MB fp16 predictions
__device__ float  g_s0[BB * JD];
__device__ float  g_s1[BB * JD];
__device__ float  g_s2[BB * JD];

__device__ __forceinline__ float softplusf(float z) {
    return z > 15.f ? z : __logf(1.f + __expf(z));
}
// ---- Blackwell packed f32x2 helpers (PTX-only; ptxas won't auto-fuse) ----
__device__ __forceinline__ ull pk2(float lo, float hi) {
    ull d; asm("mov.b64 %0, {%1, %2};" : "=l"(d) : "f"(lo), "f"(hi)); return d;
}
__device__ __forceinline__ void upk2(float& lo, float& hi, ull v) {
    asm("mov.b64 {%0, %1}, %2;" : "=f"(lo), "=f"(hi) : "l"(v));
}
__device__ __forceinline__ ull mul2(ull a, ull b) {
    ull d; asm("mul.rn.f32x2 %0, %1, %2;" : "=l"(d) : "l"(a), "l"(b)); return d;
}
__device__ __forceinline__ ull fma2(ull a, ull b, ull c) {
    ull d; asm("fma.rn.f32x2 %0, %1, %2, %3;" : "=l"(d) : "l"(a), "l"(b), "l"(c)); return d;
}

// ---------------------------------------------------------------------------
// init: zero accumulators (atomics add into them each replay)
// ---------------------------------------------------------------------------
__global__ void init_kernel() {
    int idx = blockIdx.x * blockDim.x + threadIdx.x;
    if (idx < BB * JD) { g_s0[idx] = 0.f; g_s1[idx] = 0.f; g_s2[idx] = 0.f; }
}

// ---------------------------------------------------------------------------
// pass0: pure stream. W = loc + (1e-5 + softplus(C+sraw))*eps on the fly;
//        u_hat[b,i,jd] = sum_k W[i,jd,k]*x[b,i,k] -> half2 store.
// 256 threads, thread t owns jd pair (2t, 2t+1). Block handles IPB i's.
// Inner products use packed fma.rn.f32x2 over k-pairs (x float4 == 2 f32x2).
// Only 2 KB smem -> multiple blocks/SM.
// ---------------------------------------------------------------------------
__global__ void __launch_bounds__(256) pass0_kernel(
    const float* __restrict__ x, const float* __restrict__ loc,
    const float* __restrict__ sraw, const float* __restrict__ eps)
{
    __shared__ float x_s[BB * KDIM];   // 2 KB
    const int t = threadIdx.x;
    const int i0 = blockIdx.x * IPB;

    for (int ii = 0; ii < IPB; ++ii) {
        const int i = i0 + ii;
        // 16 consecutive floats per array: jd=2t row (k0..7) then jd=2t+1 row
        const size_t wb = ((size_t)i * JD + 2 * t) * KDIM;
        float4 L[4], R[4], E[4];
        #pragma unroll
        for (int q = 0; q < 4; ++q) {
            L[q] = *(const float4*)(loc  + wb + 4 * q);
            R[q] = *(const float4*)(sraw + wb + 4 * q);
            E[q] = *(const float4*)(eps  + wb + 4 * q);
        }
        float W[16];
        #pragma unroll
        for (int q = 0; q < 4; ++q) {
            const float* l = (const float*)&L[q];
            const float* r = (const float*)&R[q];
            const float* e = (const float*)&E[q];
            #pragma unroll
            for (int u = 0; u < 4; ++u)
                W[4 * q + u] = l[u] + (1e-5f + softplusf(SP_C + r[u])) * e[u];
        }
        // pack over k-pairs: Wp0 for jd=2t, Wp1 for jd=2t+1
        ull Wp0[4], Wp1[4];
        #pragma unroll
        for (int q = 0; q < 4; ++q) {
            Wp0[q] = pk2(W[2 * q],     W[2 * q + 1]);
            Wp1[q] = pk2(W[8 + 2 * q], W[8 + 2 * q + 1]);
        }

        __syncthreads();   // previous iter's b-loop readers done
        {
            int m0 = t, m1 = t + 256;
            x_s[m0] = x[((size_t)(m0 >> 3) * ICAPS + i) * KDIM + (m0 & 7)];
            x_s[m1] = x[((size_t)(m1 >> 3) * ICAPS + i) * KDIM + (m1 & 7)];
        }
        __syncthreads();

        const float4* xs4 = (const float4*)x_s;          // [2*b], [2*b+1]
        __half2* up = (__half2*)g_uhat + (size_t)i * (JD / 2) + t;
        const size_t bstride = (size_t)ICAPS * (JD / 2); // half2 units
        #pragma unroll 4
        for (int b = 0; b < BB; ++b) {
            float4 xa = xs4[2 * b], xb = xs4[2 * b + 1]; // k0..3, k4..7
            ull x01 = pk2(xa.x, xa.y), x23 = pk2(xa.z, xa.w);
            ull x45 = pk2(xb.x, xb.y), x67 = pk2(xb.z, xb.w);
            ull a0 = mul2(Wp0[0], x01);
            ull b0 = mul2(Wp0[1], x23);
            a0 = fma2(Wp0[2], x45, a0);
            b0 = fma2(Wp0[3], x67, b0);
            ull a1 = mul2(Wp1[0], x01);
            ull b1 = mul2(Wp1[1], x23);
            a1 = fma2(Wp1[2], x45, a1);
            b1 = fma2(Wp1[3], x67, b1);
            float p0, p1, q0, q1, r0, r1, s0, s1;
            upk2(p0, p1, a0); upk2(q0, q1, b0);
            upk2(r0, r1, a1); upk2(s0, s1, b1);
            float u0 = (p0 + p1) + (q0 + q1);
            float u1 = (r0 + r1) + (s0 + s1);
            up[(size_t)b * bstride] = __floats2half2_rn(u0, u1);
        }
    }
}

// ---------------------------------------------------------------------------
// reduce_s0: s0[b,jd] = sum_i uhat[b,i,jd]. Register accumulation (thread owns
// a jd pair), i DESCENDING to hit pass0's freshest writes in L2.
// grid (BB, 8): each block sums a 256-i chunk; atomicAdd merge (4 per addr).
// ---------------------------------------------------------------------------
__global__ void __launch_bounds__(256) reduce_s0_kernel() {
    const int b = blockIdx.x, ch = blockIdx.y, t = threadIdx.x;
    const __half2* base = (const __half2*)g_uhat
                        + (size_t)b * ICAPS * (JD / 2) + t;
    const int i_hi = (ch + 1) * (ICAPS / 8) - 1;
    float ax = 0.f, ay = 0.f;
    #pragma unroll 8
    for (int s = 0; s < ICAPS / 8; ++s) {
        float2 f = __half22float2(base[(size_t)(i_hi - s) * (JD / 2)]);
        ax += f.x; ay += f.y;
    }
    atomicAdd(&g_s0[b * JD + 2 * t],     ax);
    atomicAdd(&g_s0[b * JD + 2 * t + 1], ay);
}

// ---------------------------------------------------------------------------
// route pass. Computes v in-kernel from g_s0 (and g_s1 for LAST):
//   !LAST: v = v0 = squash(s0/32)            -> accumulates s1
//    LAST: v = v0 + squash(s1)               -> accumulates s2, writes c
// ---------------------------------------------------------------------------
template<bool LAST>
__global__ void __launch_bounds__(128) route_kernel(float* __restrict__ c_out)
{
    __shared__ float v_s[JD];
    __shared__ float sp_s[4][NCAPS * 17 + 1];
    const int b = blockIdx.x;
    const int tid = threadIdx.x, lane = tid & 31, w = tid >> 5;

    if (tid < NCAPS) {   // per-j squash (redundant per block; tiny)
        float tv[DDIM]; float n = 0.f;
        const float4* s4 = (const float4*)(g_s0 + ((size_t)b * NCAPS + tid) * DDIM);
        #pragma unroll
        for (int q = 0; q < 4; ++q) {
            float4 p = s4[q];
            tv[4*q+0] = p.x * (1.f/NCAPS); tv[4*q+1] = p.y * (1.f/NCAPS);
            tv[4*q+2] = p.z * (1.f/NCAPS); tv[4*q+3] = p.w * (1.f/NCAPS);
        }
        #pragma unroll
        for (int d = 0; d < DDIM; ++d) n = fmaf(tv[d], tv[d], n);
        float sc = n / ((1.f + n) * sqrtf(n + 1e-7f));
        float vout[DDIM];
        #pragma unroll
        for (int d = 0; d < DDIM; ++d) vout[d] = tv[d] * sc;
        if (LAST) {
            float t1[DDIM]; float n1 = 0.f;
            const float4* s14 = (const float4*)(g_s1 + ((size_t)b * NCAPS + tid) * DDIM);
            #pragma unroll
            for (int q = 0; q < 4; ++q) {
                float4 p = s14[q];
                t1[4*q+0] = p.x; t1[4*q+1] = p.y; t1[4*q+2] = p.z; t1[4*q+3] = p.w;
            }
            #pragma unroll
            for (int d = 0; d < DDIM; ++d) n1 = fmaf(t1[d], t1[d], n1);
            float sc1 = n1 / ((1.f + n1) * sqrtf(n1 + 1e-7f));
            #pragma unroll
            for (int d = 0; d < DDIM; ++d) vout[d] += t1[d] * sc1;
        }
        #pragma unroll
        for (int d = 0; d < DDIM; ++d) v_s[tid * DDIM + d] = vout[d];
    }
    __syncthreads();

    float v[DDIM];
    {
        const float4* v4 = (const float4*)(v_s + lane * DDIM);
        #pragma unroll
        for (int q = 0; q < 4; ++q) {
            float4 p = v4[q];
            v[4*q+0] = p.x; v[4*q+1] = p.y; v[4*q+2] = p.z; v[4*q+3] = p.w;
        }
    }
    float sp[DDIM];
    #pragma unroll
    for (int d = 0; d < DDIM; ++d) sp[d] = 0.f;

    const int per_block = ICAPS / 16;          // gridDim.y = 16 -> 128 i
    const int per_warp  = per_block / 4;       // 32 i per warp
    const int ibase = blockIdx.y * per_block + w * per_warp;
    const __half2* ubase = (const __half2*)g_uhat
                         + (size_t)b * ICAPS * (JD/2) + lane * (DDIM/2);

    for (int it = 0; it < per_warp / 4; ++it) {
        const int i = ibase + it * 4;
        uint4 ua[4], ub[4];
        #pragma unroll
        for (int r = 0; r < 4; ++r) {
            const uint4* p = (const uint4*)(ubase + (size_t)(i + r) * (JD/2));
            ua[r] = p[0]; ub[r] = p[1];
        }
        float ev[4];
        #pragma unroll
        for (int r = 0; r < 4; ++r) {
            float bl = 0.f;
            const __half2* ha = (const __half2*)&ua[r];
            const __half2* hb = (const __half2*)&ub[r];
            #pragma unroll
            for (int q = 0; q < 4; ++q) {
                float2 f = __half22float2(ha[q]);
                bl = fmaf(f.x, v[2*q],   fmaf(f.y, v[2*q+1],   bl));
            }
            #pragma unroll
            for (int q = 0; q < 4; ++q) {
                float2 f = __half22float2(hb[q]);
                bl = fmaf(f.x, v[8+2*q], fmaf(f.y, v[8+2*q+1], bl));
            }
            ev[r] = __expf(bl);   // logits bounded: no max-subtraction needed
        }
        float t0 = ev[0], t1 = ev[1], t2 = ev[2], t3 = ev[3];
        #pragma unroll
        for (int off = 16; off; off >>= 1) {   // 4 interleaved butterflies
            t0 += __shfl_xor_sync(0xffffffffu, t0, off);
            t1 += __shfl_xor_sync(0xffffffffu, t1, off);
            t2 += __shfl_xor_sync(0xffffffffu, t2, off);
            t3 += __shfl_xor_sync(0xffffffffu, t3, off);
        }
        float sums[4] = {t0, t1, t2, t3};
        #pragma unroll
        for (int r = 0; r < 4; ++r) {
            float c = __fdividef(ev[r], sums[r]);
            const __half2* ha = (const __half2*)&ua[r];
            const __half2* hb = (const __half2*)&ub[r];
            #pragma unroll
            for (int q = 0; q < 4; ++q) {
                float2 f = __half22float2(ha[q]);
                sp[2*q]     = fmaf(c, f.x, sp[2*q]);
                sp[2*q+1]   = fmaf(c, f.y, sp[2*q+1]);
            }
            #pragma unroll
            for (int q = 0; q < 4; ++q) {
                float2 f = __half22float2(hb[q]);
                sp[8+2*q]   = fmaf(c, f.x, sp[8+2*q]);
                sp[8+2*q+1] = fmaf(c, f.y, sp[8+2*q+1]);
            }
            if (LAST)
                c_out[((size_t)b * ICAPS + i + r) * NCAPS + lane] = c;
        }
    }
    // cross-warp reduce in smem, then one REDG burst
    #pragma unroll
    for (int d = 0; d < DDIM; ++d) sp_s[w][lane * 17 + d] = sp[d];
    __syncthreads();
    float* s_out = (LAST ? g_s2 : g_s1) + (size_t)b * JD;
    #pragma unroll
    for (int q = 0; q < 4; ++q) {
        int idx = tid * 4 + q;          // 0..511
        int j = idx >> 4, d = idx & 15;
        float a = sp_s[0][j*17+d] + sp_s[1][j*17+d]
                + sp_s[2][j*17+d] + sp_s[3][j*17+d];
        atomicAdd(s_out + idx, a);
    }
}

// ---------------------------------------------------------------------------
// final squash: out_v = squash(s2)
// ---------------------------------------------------------------------------
__global__ void squash_final_kernel(float* __restrict__ out_v)
{
    int idx = blockIdx.x * blockDim.x + threadIdx.x;
    if (idx >= BB * NCAPS) return;
    float s[DDIM]; float n = 0.f;
    const float4* s4 = (const float4*)(g_s2 + (size_t)idx * DDIM);
    #pragma unroll
    for (int q = 0; q < 4; ++q) {
        float4 p = s4[q];
        s[4*q+0] = p.x; s[4*q+1] = p.y; s[4*q+2] = p.z; s[4*q+3] = p.w;
    }
    #pragma unroll
    for (int d = 0; d < DDIM; ++d) n = fmaf(s[d], s[d], n);
    float sc = n / ((1.f + n) * sqrtf(n + 1e-7f));
    float4* d4 = (float4*)(out_v + (size_t)idx * DDIM);
    #pragma unroll
    for (int q = 0; q < 4; ++q) {
        float4 o;
        o.x = s[4*q+0] * sc; o.y = s[4*q+1] * sc;
        o.z = s[4*q+2] * sc; o.w = s[4*q+3] * sc;
        d4[q] = o;
    }
}

// ---------------------------------------------------------------------------
extern "C" void kernel_launch(void* const* d_in, const int* in_sizes, int n_in,
                              void* d_out, int out_size)
{
    const float* x    = (const float*)d_in[0];
    const float* loc  = (const float*)d_in[1];
    const float* sraw = (const float*)d_in[2];
    const float* eps  = (const float*)d_in[3];
    float* out_v = (float*)d_out;                 // [B, NCAPS, DDIM]
    float* out_c = out_v + BB * NCAPS * DDIM;     // [B, ICAPS, NCAPS]

    init_kernel<<<(BB * JD + 255) / 256, 256>>>();
    pass0_kernel<<<ICAPS / IPB, 256>>>(x, loc, sraw, eps);   // 512 blocks
    reduce_s0_kernel<<<dim3(BB, 8), 256>>>();
    route_kernel<false><<<dim3(BB, 16), 128>>>(nullptr);     // iter 1 -> s1
    route_kernel<true><<<dim3(BB, 16), 128>>>(out_c);        // iter 2 -> s2, c
    squash_final_kernel<<<(BB * NCAPS + 63) / 64, 64>>>(out_v);
}